// round 1
// baseline (speedup 1.0000x reference)
#include <cuda_runtime.h>

typedef unsigned long long u64;

__device__ __forceinline__ u64 f2fma(u64 a, u64 b, u64 c) {
    u64 d;
    asm("fma.rn.f32x2 %0, %1, %2, %3;" : "=l"(d) : "l"(a), "l"(b), "l"(c));
    return d;
}
__device__ __forceinline__ u64 f2bcast(float x) {
    u64 d;
    asm("mov.b64 %0, {%1, %1};" : "=l"(d) : "f"(x));
    return d;
}
__device__ __forceinline__ float2 f2unpack(u64 v) {
    float2 r;
    asm("mov.b64 {%0, %1}, %2;" : "=f"(r.x), "=f"(r.y) : "l"(v));
    return r;
}
__device__ __forceinline__ float hswish(float x) {
    return x * __saturatef((x + 3.0f) * (1.0f / 6.0f));
}

#define P_TOTAL 409600

// Scratch (device globals: allocation-free per harness rules)
__device__ float g_y [P_TOTAL * 64];
__device__ float g_t [P_TOTAL * 64];
__device__ float g_xc[P_TOTAL * 128];

// ---------------------------------------------------------------------------
// 1x1 conv as GEMM. 256 threads. Each thread: PX=4 pixels x 16 out-channels
// (32 f32x2 accumulators). Inputs + weights staged in padded smem.
//   EPI: 0 = plain conv, 1 = BN + hard-swish
//   PRE: apply bn_cat + LeakyReLU(0.1) to inputs while staging (cv4 path)
// Smem padding: input row stride CIN+4 (banks 0,4,..,28 across warp slots),
// weight 16-float co-blocks padded to 20 (cog*20 mod 32 spreads all lanes).
// ---------------------------------------------------------------------------
template<int CIN, int COUT, int EPI, bool PRE>
__global__ void __launch_bounds__(256, 1) conv1x1_k(
    const float* __restrict__ in, const float* __restrict__ w,
    const float* __restrict__ bnp, const float* __restrict__ prebn,
    float* __restrict__ out, int ostride, int ocoff)
{
    constexpr int G    = COUT / 16;       // co-groups
    constexpr int S    = 256 / G;         // pixel slots
    constexpr int PX   = 4;
    constexpr int TP   = S * PX;          // pixels per block
    constexpr int CSTR = CIN + 4;
    constexpr int WSTR = COUT + (COUT / 16) * 4;

    extern __shared__ float sm[];
    float* in_s  = sm;                    // TP * CSTR
    float* w_s   = sm + TP * CSTR;        // CIN * WSTR
    float* pre_s = w_s + CIN * WSTR;      // 2 * CIN (PRE only)

    const int tid = threadIdx.x;
    const long long p0 = (long long)blockIdx.x * TP;

    if (PRE) {
        if (tid < CIN) {
            float g = prebn[tid], b = prebn[CIN + tid];
            float m = prebn[2 * CIN + tid], v = prebn[3 * CIN + tid];
            float sc = g * rsqrtf(v + 1e-3f);
            pre_s[tid]       = sc;
            pre_s[CIN + tid] = b - m * sc;
        }
        __syncthreads();
    }

    // stage weights (HWIO 1x1 => [CIN][COUT], COUT contiguous)
    constexpr int C4O = COUT / 4;
    for (int i = tid; i < CIN * C4O; i += 256) {
        int ci = i / C4O, c4 = i - ci * C4O;
        int co = c4 * 4;
        float4 v = ((const float4*)w)[i];
        *(float4*)&w_s[ci * WSTR + co + ((co >> 4) << 2)] = v;
    }

    // stage inputs
    constexpr int C4 = CIN / 4;
    for (int i = tid; i < TP * C4; i += 256) {
        int p = i / C4, c4 = i - p * C4;
        float4 v = ((const float4*)(in + (p0 + p) * CIN))[c4];
        if (PRE) {
            int c = c4 * 4;
            float t;
            t = pre_s[c+0]*v.x + pre_s[CIN+c+0]; v.x = t >= 0.f ? t : 0.1f*t;
            t = pre_s[c+1]*v.y + pre_s[CIN+c+1]; v.y = t >= 0.f ? t : 0.1f*t;
            t = pre_s[c+2]*v.z + pre_s[CIN+c+2]; v.z = t >= 0.f ? t : 0.1f*t;
            t = pre_s[c+3]*v.w + pre_s[CIN+c+3]; v.w = t >= 0.f ? t : 0.1f*t;
        }
        *(float4*)&in_s[p * CSTR + c4 * 4] = v;
    }
    __syncthreads();

    const int slot = tid / G;
    const int cog  = tid - slot * G;

    u64 acc[PX][8];
    #pragma unroll
    for (int i = 0; i < PX; i++)
        #pragma unroll
        for (int j = 0; j < 8; j++) acc[i][j] = 0ull;

    const float* wb = w_s + cog * 20;
    #pragma unroll 2
    for (int k = 0; k < CIN; k += 4) {
        float4 a[PX];
        #pragma unroll
        for (int i = 0; i < PX; i++)
            a[i] = *(const float4*)&in_s[(slot + i * S) * CSTR + k];
        #pragma unroll
        for (int kk = 0; kk < 4; kk++) {
            const ulonglong2* wr = (const ulonglong2*)(wb + (k + kk) * WSTR);
            u64 wv[8];
            #pragma unroll
            for (int j = 0; j < 4; j++) {
                ulonglong2 q = wr[j];
                wv[2*j] = q.x; wv[2*j+1] = q.y;
            }
            #pragma unroll
            for (int i = 0; i < PX; i++) {
                float av = (kk == 0) ? a[i].x : (kk == 1) ? a[i].y
                         : (kk == 2) ? a[i].z : a[i].w;
                u64 ab = f2bcast(av);
                #pragma unroll
                for (int j = 0; j < 8; j++) acc[i][j] = f2fma(ab, wv[j], acc[i][j]);
            }
        }
    }

    float scl[16], bia[16];
    if (EPI == 1) {
        #pragma unroll
        for (int j = 0; j < 16; j++) {
            int c = cog * 16 + j;
            float g = bnp[c], b = bnp[COUT + c];
            float m = bnp[2 * COUT + c], v = bnp[3 * COUT + c];
            scl[j] = g * rsqrtf(v + 1e-3f);
            bia[j] = b - m * scl[j];
        }
    }
    #pragma unroll
    for (int i = 0; i < PX; i++) {
        long long p = p0 + slot + i * S;
        float o[16];
        #pragma unroll
        for (int j = 0; j < 8; j++) {
            float2 v = f2unpack(acc[i][j]);
            o[2*j] = v.x; o[2*j+1] = v.y;
        }
        if (EPI == 1) {
            #pragma unroll
            for (int j = 0; j < 16; j++) {
                float t = scl[j] * o[j] + bia[j];
                o[j] = hswish(t);
            }
        }
        float* op = out + p * ostride + ocoff + cog * 16;
        #pragma unroll
        for (int j = 0; j < 4; j++)
            *(float4*)(op + 4*j) = make_float4(o[4*j], o[4*j+1], o[4*j+2], o[4*j+3]);
    }
}

// ---------------------------------------------------------------------------
// 3x3 SAME conv (64->64) + BN + hard-swish + residual add into yio.
// One block = 16x16 spatial tile of one image; halo tile (18x18x64) in smem,
// 9 taps each staging a 64x64 weight slice. Same register tiling as 1x1.
// ---------------------------------------------------------------------------
__global__ void __launch_bounds__(256, 1) conv3x3_res_k(
    const float* __restrict__ in, const float* __restrict__ w,
    const float* __restrict__ bnp, float* __restrict__ yio)
{
    constexpr int CSTR = 68;
    constexpr int WSTR = 80;
    extern __shared__ float sm[];
    float* in_s = sm;               // 324 * 68
    float* w_s  = sm + 324 * CSTR;  // 64 * 80

    const int tid = threadIdx.x;
    const int blk = blockIdx.x;              // 16 images * 10 * 10 tiles
    const int b  = blk / 100;
    const int t  = blk - b * 100;
    const int ty = t / 10, tx = t - ty * 10;
    const int y0 = ty * 16, x0 = tx * 16;
    const long long img = (long long)b * 25600;

    // load 18x18 halo tile (zero padded)
    for (int i = tid; i < 324 * 16; i += 256) {
        int r = i >> 4, c4 = i & 15;
        int iy = r / 18, ix = r - iy * 18;
        int gy = y0 + iy - 1, gx = x0 + ix - 1;
        float4 v = make_float4(0.f, 0.f, 0.f, 0.f);
        if (gy >= 0 && gy < 160 && gx >= 0 && gx < 160)
            v = ((const float4*)(in + (img + gy * 160 + gx) * 64))[c4];
        *(float4*)&in_s[r * CSTR + c4 * 4] = v;
    }

    const int slot = tid >> 2;
    const int cog  = tid & 3;

    int py[4], px[4];
    #pragma unroll
    for (int i = 0; i < 4; i++) {
        int p = slot + i * 64;
        py[i] = p >> 4; px[i] = p & 15;
    }

    u64 acc[4][8];
    #pragma unroll
    for (int i = 0; i < 4; i++)
        #pragma unroll
        for (int j = 0; j < 8; j++) acc[i][j] = 0ull;

    for (int tap = 0; tap < 9; tap++) {
        __syncthreads();   // also covers initial halo-load completion
        for (int i = tid; i < 1024; i += 256) {
            int ci = i >> 4, c4 = i & 15;
            int co = c4 * 4;
            float4 v = ((const float4*)(w + tap * 4096))[i];
            *(float4*)&w_s[ci * WSTR + co + ((co >> 4) << 2)] = v;
        }
        __syncthreads();
        const int kh = tap / 3, kw = tap - kh * 3;
        int rb[4];
        #pragma unroll
        for (int i = 0; i < 4; i++)
            rb[i] = ((py[i] + kh) * 18 + px[i] + kw) * CSTR;

        const float* wb = w_s + cog * 20;
        #pragma unroll 2
        for (int k = 0; k < 64; k += 4) {
            float4 a[4];
            #pragma unroll
            for (int i = 0; i < 4; i++)
                a[i] = *(const float4*)&in_s[rb[i] + k];
            #pragma unroll
            for (int kk = 0; kk < 4; kk++) {
                const ulonglong2* wr = (const ulonglong2*)(wb + (k + kk) * WSTR);
                u64 wv[8];
                #pragma unroll
                for (int j = 0; j < 4; j++) {
                    ulonglong2 q = wr[j];
                    wv[2*j] = q.x; wv[2*j+1] = q.y;
                }
                #pragma unroll
                for (int i = 0; i < 4; i++) {
                    float av = (kk == 0) ? a[i].x : (kk == 1) ? a[i].y
                             : (kk == 2) ? a[i].z : a[i].w;
                    u64 ab = f2bcast(av);
                    #pragma unroll
                    for (int j = 0; j < 8; j++) acc[i][j] = f2fma(ab, wv[j], acc[i][j]);
                }
            }
        }
    }

    float scl[16], bia[16];
    #pragma unroll
    for (int j = 0; j < 16; j++) {
        int c = cog * 16 + j;
        float g = bnp[c], b2 = bnp[64 + c];
        float m = bnp[128 + c], v = bnp[192 + c];
        scl[j] = g * rsqrtf(v + 1e-3f);
        bia[j] = b2 - m * scl[j];
    }
    #pragma unroll
    for (int i = 0; i < 4; i++) {
        long long gp = img + (long long)(y0 + py[i]) * 160 + (x0 + px[i]);
        float* yp = yio + gp * 64 + cog * 16;
        float o[16];
        #pragma unroll
        for (int j = 0; j < 8; j++) {
            float2 v = f2unpack(acc[i][j]);
            o[2*j] = v.x; o[2*j+1] = v.y;
        }
        #pragma unroll
        for (int j = 0; j < 16; j++) {
            float t2 = scl[j] * o[j] + bia[j];
            o[j] = hswish(t2);
        }
        #pragma unroll
        for (int j = 0; j < 4; j++) {
            float4 r = *(float4*)(yp + 4*j);
            r.x += o[4*j+0]; r.y += o[4*j+1];
            r.z += o[4*j+2]; r.w += o[4*j+3];
            *(float4*)(yp + 4*j) = r;
        }
    }
}

// ---------------------------------------------------------------------------

extern "C" void kernel_launch(void* const* d_in, const int* in_sizes, int n_in,
                              void* d_out, int out_size)
{
    (void)in_sizes; (void)n_in; (void)out_size;
    const float* x         = (const float*)d_in[0];
    const float* cv1_w     = (const float*)d_in[1];
    const float* cv1_bn    = (const float*)d_in[2];
    const float* m0_cv1_w  = (const float*)d_in[3];
    const float* m0_cv1_bn = (const float*)d_in[4];
    const float* m0_cv2_w  = (const float*)d_in[5];
    const float* m0_cv2_bn = (const float*)d_in[6];
    const float* m1_cv1_w  = (const float*)d_in[7];
    const float* m1_cv1_bn = (const float*)d_in[8];
    const float* m1_cv2_w  = (const float*)d_in[9];
    const float* m1_cv2_bn = (const float*)d_in[10];
    const float* cv3_w     = (const float*)d_in[11];
    const float* cv2p_w    = (const float*)d_in[12];
    const float* bn_cat    = (const float*)d_in[13];
    const float* cv4_w     = (const float*)d_in[14];
    const float* cv4_bn    = (const float*)d_in[15];
    float* out = (float*)d_out;

    float *py = nullptr, *pt = nullptr, *pxc = nullptr;
    cudaGetSymbolAddress((void**)&py,  g_y);
    cudaGetSymbolAddress((void**)&pt,  g_t);
    cudaGetSymbolAddress((void**)&pxc, g_xc);

    constexpr int SM_A = (256*132 + 128*80) * 4;            // 176128 B
    constexpr int SM_B = (256*68  + 64*80)  * 4;            //  90112 B
    constexpr int SM_C = (324*68  + 64*80)  * 4;            // 108608 B
    constexpr int SM_D = (128*132 + 128*160 + 256) * 4;     // 150528 B

    cudaFuncSetAttribute(conv1x1_k<128, 64,1,false>, cudaFuncAttributeMaxDynamicSharedMemorySize, SM_A);
    cudaFuncSetAttribute(conv1x1_k< 64, 64,1,false>, cudaFuncAttributeMaxDynamicSharedMemorySize, SM_B);
    cudaFuncSetAttribute(conv1x1_k< 64, 64,0,false>, cudaFuncAttributeMaxDynamicSharedMemorySize, SM_B);
    cudaFuncSetAttribute(conv1x1_k<128, 64,0,false>, cudaFuncAttributeMaxDynamicSharedMemorySize, SM_A);
    cudaFuncSetAttribute(conv1x1_k<128,128,1,true >, cudaFuncAttributeMaxDynamicSharedMemorySize, SM_D);
    cudaFuncSetAttribute(conv3x3_res_k,              cudaFuncAttributeMaxDynamicSharedMemorySize, SM_C);

    // cv1: 1x1 128->64, BN+hswish
    conv1x1_k<128,64,1,false><<<1600, 256, SM_A>>>(x,  cv1_w,    cv1_bn,    nullptr, py, 64, 0);
    // bottleneck 0
    conv1x1_k< 64,64,1,false><<<1600, 256, SM_B>>>(py, m0_cv1_w, m0_cv1_bn, nullptr, pt, 64, 0);
    conv3x3_res_k<<<1600, 256, SM_C>>>(pt, m0_cv2_w, m0_cv2_bn, py);
    // bottleneck 1
    conv1x1_k< 64,64,1,false><<<1600, 256, SM_B>>>(py, m1_cv1_w, m1_cv1_bn, nullptr, pt, 64, 0);
    conv3x3_res_k<<<1600, 256, SM_C>>>(pt, m1_cv2_w, m1_cv2_bn, py);
    // x1 = conv1x1(y, cv3_w) -> xc[:, 0:64]   (plain conv)
    conv1x1_k< 64,64,0,false><<<1600, 256, SM_B>>>(py, cv3_w,  nullptr, nullptr, pxc, 128, 0);
    // x2 = conv1x1(x, cv2p_w) -> xc[:, 64:128] (plain conv)
    conv1x1_k<128,64,0,false><<<1600, 256, SM_A>>>(x,  cv2p_w, nullptr, nullptr, pxc, 128, 64);
    // cv4: bn_cat+leaky on input, 1x1 128->128, BN+hswish -> out
    conv1x1_k<128,128,1,true><<<3200, 256, SM_D>>>(pxc, cv4_w, cv4_bn, bn_cat, out, 128, 0);
}